// round 13
// baseline (speedup 1.0000x reference)
#include <cuda_runtime.h>

// ParametricInterpolation — numerics FROZEN (bit-exact vs reference since R8):
//   p_k = RN(params_k * RN(1/fl32(scaler_k)))   (XLA divide->recip-mul)
//   i2 = RN(i*i), i3 = RN(i2*i), i4 = RN(i2*i2) (integer_pow sq-and-mul)
//   c  = RN(p0*i4); fma(p1,i3); fma(p2,i2); fma(p3,i); + p4  (ascending fma)
//   round-half-even; k = c - ci; pos = clip(n - ci, 1, 2047)
//   out = RN(RN(x1*RN(1-k)) + RN(x2*k))          (non-contracted lerp)
//
// Perf changes vs R11 (best structure):
//  * __launch_bounds__(256,6): 42-reg budget, the 32-value live set stays in
//    registers (R11/R12 spilled under the 32-reg cap -> L1=41% local traffic).
//  * No cvt-pipe ops in the index path: rintf/F2I replaced by the 2^23+2^22
//    magic-number round (bit-identical round-half-even for |c| < 2^22; curve
//    magnitude here is ~1e4) with integer extraction from the float bits;
//    fi generated by an exact float recurrence instead of I2F.

#define SIG_LEN 2048
#define PARTS   (SIG_LEN / 256)   // 8
#define MAGIC_F 12582912.0f       // 2^23 + 2^22
#define MAGIC_I 0x4B400000

__global__ __launch_bounds__(256, 6)
void pik_kernel(const float* __restrict__ x,
                const float* __restrict__ params,
                float* __restrict__ out)
{
    const int b   = blockIdx.x;
    const int tid = threadIdx.x;

    // Warp-uniform param loads -> broadcast, L1-resident.
    const float* pb = params + (size_t)b * 5;
    const float p0 = __fmul_rn(__ldg(pb + 0), (float)(1.0 / (double)1e12f));
    const float p1 = __fmul_rn(__ldg(pb + 1), (float)(1.0 / (double)1e8f));
    const float p2 = __fmul_rn(__ldg(pb + 2), (float)(1.0 / (double)1e4f));
    const float p3 =            __ldg(pb + 3);   // inv = 1.0 exactly
    const float p4 = __fmul_rn(__ldg(pb + 4), (float)(1.0 / (double)10.0f));

    const float* xrow = x   + (size_t)b * SIG_LEN;
    float*       orow = out + (size_t)b * SIG_LEN;

    const float fi0 = (float)tid;   // single I2F for the whole thread

    int   pos[PARTS];
    float kk [PARTS];

    // Phase 1: indices/weights for all 8 parts (ALU/FMA only, no cvt ops).
    #pragma unroll
    for (int part = 0; part < PARTS; ++part) {
        // exact: fi == (float)(part*256 + tid)  (integers < 2^24)
        const float fi = fi0 + (float)(part * 256);

        const float i2 = __fmul_rn(fi, fi);   // exact
        const float i3 = __fmul_rn(i2, fi);
        const float i4 = __fmul_rn(i2, i2);

        float c = __fmul_rn(p0, i4);          // ascending-k fma chain
        c = __fmaf_rn(p1, i3, c);
        c = __fmaf_rn(p2, i2, c);
        c = __fmaf_rn(p3, fi, c);
        c = __fadd_rn(c, p4);

        // round-half-even via magic number (== rintf for |c| < 2^22)
        const float y  = __fadd_rn(c, MAGIC_F);
        const float ci = __fsub_rn(y, MAGIC_F);
        const int   ci_i = __float_as_int(y) - MAGIC_I;

        kk[part] = __fadd_rn(c, -ci);

        int p = (part * 256 + tid) - ci_i;    // integer index path
        p = max(1, min(SIG_LEN - 1, p));
        pos[part] = p;
    }

    // Phase 2: 16 independent gather LDGs in flight.
    float x1v[PARTS], x2v[PARTS];
    #pragma unroll
    for (int part = 0; part < PARTS; ++part) {
        x1v[part] = __ldg(xrow + pos[part]);
        x2v[part] = __ldg(xrow + pos[part] - 1);
    }

    // Phase 3: lerp + coalesced stores.
    #pragma unroll
    for (int part = 0; part < PARTS; ++part) {
        const int n = part * 256 + tid;
        const float k  = kk[part];
        const float w1 = __fsub_rn(1.0f, k);  // non-contracted lerp
        orow[n] = __fadd_rn(__fmul_rn(x1v[part], w1), __fmul_rn(x2v[part], k));
    }
}

extern "C" void kernel_launch(void* const* d_in, const int* in_sizes, int n_in,
                              void* d_out, int out_size)
{
    const float* x;
    const float* params;
    if (n_in >= 2 && in_sizes[0] < in_sizes[1]) {
        params = (const float*)d_in[0];
        x      = (const float*)d_in[1];
    } else {
        x      = (const float*)d_in[0];
        params = (const float*)d_in[1];
    }
    float* out = (float*)d_out;

    const int batch = 16384;
    pik_kernel<<<batch, 256>>>(x, params, out);
}

// round 14
// speedup vs baseline: 1.0434x; 1.0434x over previous
#include <cuda_runtime.h>

// ParametricInterpolation — numerics FROZEN (bit-exact vs reference since R8):
//   p_k = RN(params_k * RN(1/fl32(scaler_k)))   (XLA divide->recip-mul)
//   i2 = RN(i*i), i3 = RN(i2*i), i4 = RN(i2*i2) (integer_pow sq-and-mul)
//   c  = RN(p0*i4); fma(p1,i3); fma(p2,i2); fma(p3,i); + p4  (ascending fma)
//   round-half-even (magic 2^23+2^22, == rintf for |c| < 2^22)
//   k = c - ci; pos = clip(n - ci, 1, 2047)
//   out = RN(RN(x1*RN(1-k)) + RN(x2*k))          (non-contracted lerp)
//
// R14 structure (vs R11 best): occupancy-8 (32-reg cap) kept, but
//  * kk[] eliminated — k is recomputed bit-identically in the store phase,
//    cutting 8 live registers so the load phase fits the cap without spills;
//  * each part's gather LDGs issue immediately after its pos (earlier issue,
//    later parts' curve math covers the latency); pos[] dies at load issue.

#define SIG_LEN 2048
#define PARTS   (SIG_LEN / 256)   // 8
#define MAGIC_F 12582912.0f       // 2^23 + 2^22
#define MAGIC_I 0x4B400000

__global__ __launch_bounds__(256, 8)
void pik_kernel(const float* __restrict__ x,
                const float* __restrict__ params,
                float* __restrict__ out)
{
    const int b   = blockIdx.x;
    const int tid = threadIdx.x;

    // Warp-uniform param loads -> broadcast, L1-resident.
    const float* pb = params + (size_t)b * 5;
    const float p0 = __fmul_rn(__ldg(pb + 0), (float)(1.0 / (double)1e12f));
    const float p1 = __fmul_rn(__ldg(pb + 1), (float)(1.0 / (double)1e8f));
    const float p2 = __fmul_rn(__ldg(pb + 2), (float)(1.0 / (double)1e4f));
    const float p3 =            __ldg(pb + 3);   // inv = 1.0 exactly
    const float p4 = __fmul_rn(__ldg(pb + 4), (float)(1.0 / (double)10.0f));

    const float* xrow = x   + (size_t)b * SIG_LEN;
    float*       orow = out + (size_t)b * SIG_LEN;

    const float fi0 = (float)tid;   // single I2F per thread

    float x1v[PARTS], x2v[PARTS];

    // Phase 1: per part — curve, pos, and IMMEDIATE gather issue.
    #pragma unroll
    for (int part = 0; part < PARTS; ++part) {
        const float fi = fi0 + (float)(part * 256);   // exact

        const float i2 = __fmul_rn(fi, fi);   // exact
        const float i3 = __fmul_rn(i2, fi);
        const float i4 = __fmul_rn(i2, i2);

        float c = __fmul_rn(p0, i4);          // ascending-k fma chain
        c = __fmaf_rn(p1, i3, c);
        c = __fmaf_rn(p2, i2, c);
        c = __fmaf_rn(p3, fi, c);
        c = __fadd_rn(c, p4);

        // round-half-even via magic number; integer index from float bits
        const float y    = __fadd_rn(c, MAGIC_F);
        const int   ci_i = __float_as_int(y) - MAGIC_I;

        int p = (part * 256 + tid) - ci_i;
        p = max(1, min(SIG_LEN - 1, p));

        x1v[part] = __ldg(xrow + p);          // issue now; land during later parts
        x2v[part] = __ldg(xrow + p - 1);
    }

    // Phase 2: recompute k bit-identically, lerp, coalesced stores.
    #pragma unroll
    for (int part = 0; part < PARTS; ++part) {
        const float fi = fi0 + (float)(part * 256);

        const float i2 = __fmul_rn(fi, fi);
        const float i3 = __fmul_rn(i2, fi);
        const float i4 = __fmul_rn(i2, i2);

        float c = __fmul_rn(p0, i4);
        c = __fmaf_rn(p1, i3, c);
        c = __fmaf_rn(p2, i2, c);
        c = __fmaf_rn(p3, fi, c);
        c = __fadd_rn(c, p4);

        const float y  = __fadd_rn(c, MAGIC_F);
        const float ci = __fsub_rn(y, MAGIC_F);
        const float k  = __fadd_rn(c, -ci);

        const float w1 = __fsub_rn(1.0f, k);  // non-contracted lerp
        orow[part * 256 + tid] =
            __fadd_rn(__fmul_rn(x1v[part], w1), __fmul_rn(x2v[part], k));
    }
}

extern "C" void kernel_launch(void* const* d_in, const int* in_sizes, int n_in,
                              void* d_out, int out_size)
{
    const float* x;
    const float* params;
    if (n_in >= 2 && in_sizes[0] < in_sizes[1]) {
        params = (const float*)d_in[0];
        x      = (const float*)d_in[1];
    } else {
        x      = (const float*)d_in[0];
        params = (const float*)d_in[1];
    }
    float* out = (float*)d_out;

    const int batch = 16384;
    pik_kernel<<<batch, 256>>>(x, params, out);
}

// round 15
// speedup vs baseline: 1.0794x; 1.0344x over previous
#include <cuda_runtime.h>

// ParametricInterpolation — numerics FROZEN (bit-exact vs reference since R8):
//   p_k = RN(params_k * RN(1/fl32(scaler_k)))   (XLA divide->recip-mul)
//   i2 = RN(i*i), i3 = RN(i2*i), i4 = RN(i2*i2) (integer_pow sq-and-mul)
//   c  = RN(p0*i4); fma(p1,i3); fma(p2,i2); fma(p3,i); + p4  (ascending fma)
//   round-half-even (magic 2^23+2^22, == rintf for |c| < 2^22)
//   k = c - ci; pos = clip(n - ci, 1, 2047)
//   out = RN(RN(x1*RN(1-k)) + RN(x2*k))          (non-contracted lerp)
//
// R15 structure:
//  * early gather issue per part (R14) + kk[] kept in registers (R11) — no
//    quartic recompute, ~120 fewer issued instr/thread;
//  * __launch_bounds__(256,7): 36-reg budget fits the 24-float live set
//    without spills at 87.5% theoretical occupancy;
//  * __stcs evict-first stores: output is write-once, keep it from churning
//    L2 so the gather/read stream stays resident.

#define SIG_LEN 2048
#define PARTS   (SIG_LEN / 256)   // 8
#define MAGIC_F 12582912.0f       // 2^23 + 2^22
#define MAGIC_I 0x4B400000

__global__ __launch_bounds__(256, 7)
void pik_kernel(const float* __restrict__ x,
                const float* __restrict__ params,
                float* __restrict__ out)
{
    const int b   = blockIdx.x;
    const int tid = threadIdx.x;

    // Warp-uniform param loads -> broadcast, L1-resident.
    const float* pb = params + (size_t)b * 5;
    const float p0 = __fmul_rn(__ldg(pb + 0), (float)(1.0 / (double)1e12f));
    const float p1 = __fmul_rn(__ldg(pb + 1), (float)(1.0 / (double)1e8f));
    const float p2 = __fmul_rn(__ldg(pb + 2), (float)(1.0 / (double)1e4f));
    const float p3 =            __ldg(pb + 3);   // inv = 1.0 exactly
    const float p4 = __fmul_rn(__ldg(pb + 4), (float)(1.0 / (double)10.0f));

    const float* xrow = x   + (size_t)b * SIG_LEN;
    float*       orow = out + (size_t)b * SIG_LEN;

    const float fi0 = (float)tid;   // single I2F per thread

    float kk [PARTS];
    float x1v[PARTS], x2v[PARTS];

    // Phase 1: per part — curve, k, pos, IMMEDIATE gather issue.
    #pragma unroll
    for (int part = 0; part < PARTS; ++part) {
        const float fi = fi0 + (float)(part * 256);   // exact

        const float i2 = __fmul_rn(fi, fi);   // exact
        const float i3 = __fmul_rn(i2, fi);
        const float i4 = __fmul_rn(i2, i2);

        float c = __fmul_rn(p0, i4);          // ascending-k fma chain
        c = __fmaf_rn(p1, i3, c);
        c = __fmaf_rn(p2, i2, c);
        c = __fmaf_rn(p3, fi, c);
        c = __fadd_rn(c, p4);

        // round-half-even via magic number; int index from float bits
        const float y    = __fadd_rn(c, MAGIC_F);
        const float ci   = __fsub_rn(y, MAGIC_F);
        const int   ci_i = __float_as_int(y) - MAGIC_I;

        kk[part] = __fadd_rn(c, -ci);

        int p = (part * 256 + tid) - ci_i;
        p = max(1, min(SIG_LEN - 1, p));

        x1v[part] = __ldg(xrow + p);          // issue now; later parts cover latency
        x2v[part] = __ldg(xrow + p - 1);
    }

    // Phase 2: lerp + streaming (evict-first) coalesced stores.
    #pragma unroll
    for (int part = 0; part < PARTS; ++part) {
        const float k  = kk[part];
        const float w1 = __fsub_rn(1.0f, k);  // non-contracted lerp
        const float v  = __fadd_rn(__fmul_rn(x1v[part], w1),
                                   __fmul_rn(x2v[part], k));
        __stcs(orow + part * 256 + tid, v);
    }
}

extern "C" void kernel_launch(void* const* d_in, const int* in_sizes, int n_in,
                              void* d_out, int out_size)
{
    const float* x;
    const float* params;
    if (n_in >= 2 && in_sizes[0] < in_sizes[1]) {
        params = (const float*)d_in[0];
        x      = (const float*)d_in[1];
    } else {
        x      = (const float*)d_in[0];
        params = (const float*)d_in[1];
    }
    float* out = (float*)d_out;

    const int batch = 16384;
    pik_kernel<<<batch, 256>>>(x, params, out);
}